// round 13
// baseline (speedup 1.0000x reference)
#include <cuda_runtime.h>
#include <cuda_bf16.h>
#include <cstdint>

#define Bsz 256
#define Dd  256
#define Tt  512
#define Hh  512
#define G4  2048
#define NBLK 128
#define PADK 520   // recurrence tiles: padded row (bf16 elems)
#define PADD 264   // xgate tiles: padded row for K=256
#define CSTR 72    // xgate output smem stride (floats)

typedef unsigned long long ull;

// ---------------- scratch (device globals; no allocs allowed) ----------------
__device__ float g_xg[(size_t)Tt * Bsz * G4];          // [t][b][P] permuted, bias folded
__device__ __nv_bfloat16 g_xT[(size_t)Bsz * Tt * Dd];  // x transposed+bf16 [b][t][d]
__device__ __nv_bfloat16 g_Wb[G4 * Dd];                // W_ih bf16, permuted rows [P][d]
__device__ float g_bias[G4];                           // b_ih+b_hh permuted
__device__ __nv_bfloat16 g_hA[Bsz * Hh];               // h ping-pong, [b][k] bf16
__device__ __nv_bfloat16 g_hB[Bsz * Hh];
__device__ float g_part[(size_t)Tt * Bsz * 32];        // per-(t,b) partial logits
__device__ unsigned g_flags[NBLK];                     // per-block step flags (4 groups of 32)

// Permutation: storage col P -> original gate-row j = g*512 + U
// P = nt*64 + 32*a + 2*u + e   with  g = 2a+e,  U = nt*16 + u
__device__ __forceinline__ int orig_j(int P) {
    int nt = P >> 6, c = P & 63;
    int a = c >> 5, u = (c & 31) >> 1, e = c & 1;
    return (2 * a + e) * Hh + nt * 16 + u;
}

__device__ __forceinline__ float sigf(float x) { return 1.0f / (1.0f + __expf(-x)); }
__device__ __forceinline__ float tanhf_fast(float x) {
    return 1.0f - 2.0f / (__expf(2.0f * x) + 1.0f);
}
__device__ __forceinline__ uint32_t smem_u32(const void* p) {
    uint32_t a;
    asm("{ .reg .u64 t; cvta.to.shared.u64 t, %1; cvt.u32.u64 %0, t; }" : "=r"(a) : "l"(p));
    return a;
}
// volatile L2 load for spin-polling (must NOT be hoisted/CSE'd)
__device__ __forceinline__ unsigned ldcg_poll(const unsigned* p) {
    unsigned v;
    asm volatile("ld.global.cg.u32 %0, [%1];" : "=r"(v) : "l"(p) : "memory");
    return v;
}

#define LDSM4(r0, r1, r2, r3, addr)                                               \
    asm volatile("ldmatrix.sync.aligned.m8n8.x4.shared.b16 {%0,%1,%2,%3}, [%4];"  \
                 : "=r"(r0), "=r"(r1), "=r"(r2), "=r"(r3) : "r"(addr))

#define MMA16816(d0, d1, d2, d3, a0, a1, a2, a3, b0, b1)                          \
    asm volatile("mma.sync.aligned.m16n8k16.row.col.f32.bf16.bf16.f32 "           \
                 "{%0,%1,%2,%3}, {%4,%5,%6,%7}, {%8,%9}, {%0,%1,%2,%3};"          \
                 : "+f"(d0), "+f"(d1), "+f"(d2), "+f"(d3)                         \
                 : "r"(a0), "r"(a1), "r"(a2), "r"(a3), "r"(b0), "r"(b1))

#define CP_ASYNC16(dst, src)                                                      \
    asm volatile("cp.async.cg.shared.global [%0], [%1], 16;" :: "r"(dst), "l"(src))
#define CP_COMMIT()  asm volatile("cp.async.commit_group;")
#define CP_WAIT(n)   asm volatile("cp.async.wait_group %0;" :: "n"(n))

// ---------------- init ----------------
__global__ void init_state() {
    int idx = blockIdx.x * blockDim.x + threadIdx.x;
    if (idx < Bsz * Hh / 2) ((unsigned*)g_hA)[idx] = 0u;
    if (idx < NBLK) g_flags[idx] = 0u;
}

// ---------------- convert x: [b][d][t] fp32 -> [b][t][d] bf16 ----------------
__global__ void __launch_bounds__(256) convert_x(const float* __restrict__ x) {
    __shared__ float tile[32][33];
    const int t0 = blockIdx.x * 32;
    const int d0 = blockIdx.y * 32;
    const int b  = blockIdx.z;
    const int tx = threadIdx.x & 31, ty = threadIdx.x >> 5;   // 32 x 8
    const float* xb = x + (size_t)b * Dd * Tt;
#pragma unroll
    for (int r = 0; r < 4; r++)
        tile[ty + r * 8][tx] = xb[(size_t)(d0 + ty + r * 8) * Tt + t0 + tx];
    __syncthreads();
    __nv_bfloat16* dst = g_xT + (size_t)b * Tt * Dd;
#pragma unroll
    for (int r = 0; r < 4; r++)
        dst[(size_t)(t0 + ty + r * 8) * Dd + d0 + tx] = __float2bfloat16(tile[tx][ty + r * 8]);
}

// ---------------- convert W_ih (permuted rows) + bias ----------------
__global__ void __launch_bounds__(256) convert_w(const float* __restrict__ Wih,
                                                 const float* __restrict__ bih,
                                                 const float* __restrict__ bhh) {
    int idx = blockIdx.x * blockDim.x + threadIdx.x;     // 524288 threads
    if (idx < G4 * Dd) {
        int P = idx >> 8, d = idx & 255;
        g_Wb[idx] = __float2bfloat16(Wih[(size_t)orig_j(P) * Dd + d]);
    }
    if (idx < G4) {
        int oj = orig_j(idx);
        g_bias[idx] = bih[oj] + bhh[oj];
    }
}

// ---------------- xgate GEMM (bf16 HMMA): per b, (T x D) @ (D x P) ----------------
// grid (32 P-tiles, 8 t-tiles, 256 b), 128 threads. Tile M=64,N=64,K=256.
__global__ void __launch_bounds__(128) xgate_mma(int dummy) {
    extern __shared__ __align__(16) __nv_bfloat16 smem[];
    __nv_bfloat16* A_s = smem;                    // [64][PADD]  (overlaid by C_s later)
    __nv_bfloat16* B_s = smem + 64 * PADD;        // [64][PADD]
    float* C_s   = (float*)smem;                  // [64][CSTR]
    float* bias_s = (float*)(smem + 2 * 64 * PADD);  // [64]

    const int tid = threadIdx.x;
    const int w = tid >> 5, lane = tid & 31;
    const int P0 = blockIdx.x * 64;
    const int t0 = blockIdx.y * 64;
    const int b  = blockIdx.z;

    if (tid < 64) bias_s[tid] = g_bias[P0 + tid];

    // stage A (x rows) and B (W rows)
    {
        const __nv_bfloat16* asrc = g_xT + ((size_t)b * Tt + t0) * Dd;
#pragma unroll
        for (int i = 0; i < 16; ++i) {
            int idx = tid + i * 128;
            int m = idx >> 5, k8 = (idx & 31) << 3;
            *(uint4*)(A_s + m * PADD + k8) = *(const uint4*)(asrc + (size_t)m * Dd + k8);
        }
        const __nv_bfloat16* bsrc = g_Wb + (size_t)P0 * Dd;
#pragma unroll
        for (int i = 0; i < 16; ++i) {
            int idx = tid + i * 128;
            int n = idx >> 5, k8 = (idx & 31) << 3;
            *(uint4*)(B_s + n * PADD + k8) = *(const uint4*)(bsrc + (size_t)n * Dd + k8);
        }
    }
    __syncthreads();

    const uint32_t smA = smem_u32(A_s);
    const uint32_t smB = smem_u32(B_s);
    const uint32_t a_addr0 = smA + (uint32_t)((w * 16 + (lane & 15)) * PADD * 2
                                              + (lane >> 4) * 16);
    const int grp = lane >> 3;
    const uint32_t b_addr0 = smB + (uint32_t)((((grp >> 1) * 8) + (lane & 7)) * PADD * 2
                                              + (grp & 1) * 16);

    float d[8][4];
#pragma unroll
    for (int s = 0; s < 8; s++)
#pragma unroll
        for (int r = 0; r < 4; r++) d[s][r] = 0.0f;

#pragma unroll 4
    for (int kc = 0; kc < 16; ++kc) {
        uint32_t a0, a1, a2, a3;
        LDSM4(a0, a1, a2, a3, a_addr0 + kc * 32);
#pragma unroll
        for (int v = 0; v < 4; ++v) {
            uint32_t r0, r1, r2, r3;
            LDSM4(r0, r1, r2, r3, b_addr0 + (uint32_t)(v * 16 * PADD * 2) + kc * 32);
            MMA16816(d[2 * v][0], d[2 * v][1], d[2 * v][2], d[2 * v][3],
                     a0, a1, a2, a3, r0, r1);
            MMA16816(d[2 * v + 1][0], d[2 * v + 1][1], d[2 * v + 1][2], d[2 * v + 1][3],
                     a0, a1, a2, a3, r2, r3);
        }
    }
    __syncthreads();   // done reading A_s; reuse as C_s

    // dump fragments: thread (q,p) rows w*16+q(+8), cols 16v+8e+2p,+1
    const int q = lane >> 2, p = lane & 3;
#pragma unroll
    for (int v = 0; v < 4; ++v)
#pragma unroll
        for (int e = 0; e < 2; ++e) {
            int j = 2 * v + e, c = 16 * v + 8 * e + 2 * p;
            *(float2*)(C_s + (w * 16 + q) * CSTR + c)     = make_float2(d[j][0], d[j][1]);
            *(float2*)(C_s + (w * 16 + q + 8) * CSTR + c) = make_float2(d[j][2], d[j][3]);
        }
    __syncthreads();

    // coalesced copy-out with bias
    {
        int r = tid >> 1, half = tid & 1, c0 = half * 32;
        float* dst = g_xg + ((size_t)(t0 + r) * Bsz + b) * G4 + P0 + c0;
        const float* src = C_s + r * CSTR + c0;
#pragma unroll
        for (int qq = 0; qq < 8; ++qq) {
            float4 v = *(const float4*)(src + 4 * qq);
            v.x += bias_s[c0 + 4 * qq + 0];
            v.y += bias_s[c0 + 4 * qq + 1];
            v.z += bias_s[c0 + 4 * qq + 2];
            v.w += bias_s[c0 + 4 * qq + 3];
            *(float4*)(dst + 4 * qq) = v;
        }
    }
}

// ---------------- persistent HMMA LSTM ----------------
// 128 blocks x 128 threads. block = (m-quarter: 64 batch) x (nt: 16 units -> 64 cols).
// cp.async two-half pipelined A staging; x_gates prefetched one step ahead.
// Barrier: per-group (same mq, 32 blocks) flag array + ballot poll — no atomics.
__global__ void __launch_bounds__(128, 1) lstm_persist(const float* __restrict__ Whh,
                                                       const float* __restrict__ Wmlp) {
    extern __shared__ __align__(16) __nv_bfloat16 smem[];
    __nv_bfloat16* A_s = smem;                    // [64][PADK]
    __nv_bfloat16* B_s = smem + 64 * PADK;        // [64][PADK]

    const int tid = threadIdx.x;
    const int w = tid >> 5, lane = tid & 31;
    const int mq = blockIdx.x >> 5;               // 0..3  (batch quarter = barrier group)
    const int nt = blockIdx.x & 31;               // 0..31
    const int m0 = mq * 64;
    const int n0u = nt * 16;

    // One-time: stage W tile (permuted cols, bf16).
    for (int idx = tid; idx < 64 * 512; idx += 128) {
        int n = idx >> 9, k = idx & 511;
        int a = n >> 5, u = (n & 31) >> 1, e = n & 1;
        int row = (2 * a + e) * Hh + n0u + u;
        B_s[n * PADK + k] = __float2bfloat16(Whh[(size_t)row * Hh + k]);
    }

    const int q = lane >> 2, p = lane & 3;
    const int b1 = m0 + w * 16 + q;
    const int b2 = b1 + 8;
    float c1[4], c2[4], wmv[4];
#pragma unroll
    for (int s = 0; s < 4; s++) {
        c1[s] = 0.0f; c2[s] = 0.0f;
        wmv[s] = Wmlp[n0u + 4 * s + p];
    }

    const uint32_t smA = smem_u32(A_s);
    const uint32_t smB = smem_u32(B_s);
    const uint32_t a_addr0 = smA + (uint32_t)((w * 16 + (lane & 15)) * PADK * 2
                                              + (lane >> 4) * 16);
    const int grp = lane >> 3;
    const uint32_t b_addr0 = smB + (uint32_t)((((grp >> 1) * 8) + (lane & 7)) * PADK * 2
                                              + (grp & 1) * 16);

    // x prefetch registers: [lo/hi][b1/b2][s]
    float2 xr[2][2][4];
    {
        const float* xb1 = g_xg + ((size_t)0 * Bsz + b1) * G4 + nt * 64;
        const float* xb2 = xb1 + (size_t)(b2 - b1) * G4;
#pragma unroll
        for (int s = 0; s < 4; ++s) {
            int u = 4 * s + p;
            xr[0][0][s] = __ldcs((const float2*)(xb1 + 2 * u));
            xr[1][0][s] = __ldcs((const float2*)(xb1 + 32 + 2 * u));
            xr[0][1][s] = __ldcs((const float2*)(xb2 + 2 * u));
            xr[1][1][s] = __ldcs((const float2*)(xb2 + 32 + 2 * u));
        }
    }
    __syncthreads();

    for (int t = 0; t < Tt; ++t) {
        const __nv_bfloat16* hprev = (t & 1) ? g_hB : g_hA;
        __nv_bfloat16*       hnext = (t & 1) ? g_hA : g_hB;

        // ---- stage A via cp.async, two K-halves ----
#pragma unroll
        for (int i = 0; i < 16; ++i) {
            int idx = tid + i * 128;
            int m = idx >> 5, k8 = (idx & 31) << 3;      // k 0..255
            CP_ASYNC16(smA + (uint32_t)(m * PADK + k8) * 2,
                       hprev + (size_t)(m0 + m) * Hh + k8);
        }
        CP_COMMIT();
#pragma unroll
        for (int i = 0; i < 16; ++i) {
            int idx = tid + i * 128;
            int m = idx >> 5, k8 = ((idx & 31) << 3) + 256;  // k 256..511
            CP_ASYNC16(smA + (uint32_t)(m * PADK + k8) * 2,
                       hprev + (size_t)(m0 + m) * Hh + k8);
        }
        CP_COMMIT();

        float d[8][4];
#pragma unroll
        for (int s = 0; s < 8; s++)
#pragma unroll
            for (int r = 0; r < 4; r++) d[s][r] = 0.0f;

        CP_WAIT(1);
        __syncthreads();
#pragma unroll 4
        for (int kc = 0; kc < 16; ++kc) {
            uint32_t a0, a1, a2, a3;
            LDSM4(a0, a1, a2, a3, a_addr0 + kc * 32);
#pragma unroll
            for (int v = 0; v < 4; ++v) {
                uint32_t r0, r1, r2, r3;
                LDSM4(r0, r1, r2, r3, b_addr0 + (uint32_t)(v * 16 * PADK * 2) + kc * 32);
                MMA16816(d[2 * v][0], d[2 * v][1], d[2 * v][2], d[2 * v][3],
                         a0, a1, a2, a3, r0, r1);
                MMA16816(d[2 * v + 1][0], d[2 * v + 1][1], d[2 * v + 1][2], d[2 * v + 1][3],
                         a0, a1, a2, a3, r2, r3);
            }
        }
        CP_WAIT(0);
        __syncthreads();
#pragma unroll 4
        for (int kc = 16; kc < 32; ++kc) {
            uint32_t a0, a1, a2, a3;
            LDSM4(a0, a1, a2, a3, a_addr0 + kc * 32);
#pragma unroll
            for (int v = 0; v < 4; ++v) {
                uint32_t r0, r1, r2, r3;
                LDSM4(r0, r1, r2, r3, b_addr0 + (uint32_t)(v * 16 * PADK * 2) + kc * 32);
                MMA16816(d[2 * v][0], d[2 * v][1], d[2 * v][2], d[2 * v][3],
                         a0, a1, a2, a3, r0, r1);
                MMA16816(d[2 * v + 1][0], d[2 * v + 1][1], d[2 * v + 1][2], d[2 * v + 1][3],
                         a0, a1, a2, a3, r2, r3);
            }
        }

        // ---- epilogue (x already in registers) ----
        float psum1 = 0.0f, psum2 = 0.0f;
#pragma unroll
        for (int s = 0; s < 4; ++s) {
            int u = 4 * s + p;
            {
                float gi = sigf(d[s][0] + xr[0][0][s].x);
                float gf = sigf(d[s][1] + xr[0][0][s].y);
                float gg = tanhf_fast(d[s + 4][0] + xr[1][0][s].x);
                float go = sigf(d[s + 4][1] + xr[1][0][s].y);
                float cn = gf * c1[s] + gi * gg;
                c1[s] = cn;
                float hn = go * tanhf_fast(cn);
                hnext[(size_t)b1 * Hh + n0u + u] = __float2bfloat16(hn);
                psum1 += hn * wmv[s];
            }
            {
                float gi = sigf(d[s][2] + xr[0][1][s].x);
                float gf = sigf(d[s][3] + xr[0][1][s].y);
                float gg = tanhf_fast(d[s + 4][2] + xr[1][1][s].x);
                float go = sigf(d[s + 4][3] + xr[1][1][s].y);
                float cn = gf * c2[s] + gi * gg;
                c2[s] = cn;
                float hn = go * tanhf_fast(cn);
                hnext[(size_t)b2 * Hh + n0u + u] = __float2bfloat16(hn);
                psum2 += hn * wmv[s];
            }
        }
        psum1 += __shfl_xor_sync(0xffffffffu, psum1, 1);
        psum1 += __shfl_xor_sync(0xffffffffu, psum1, 2);
        psum2 += __shfl_xor_sync(0xffffffffu, psum2, 1);
        psum2 += __shfl_xor_sync(0xffffffffu, psum2, 2);
        if (p == 0) {
            g_part[((size_t)t * Bsz + b1) * 32 + nt] = psum1;
            g_part[((size_t)t * Bsz + b2) * 32 + nt] = psum2;
        }

        // ---- group barrier: publish flag, prefetch next x, ballot-poll group ----
        __threadfence();
        __syncthreads();
        if (tid == 0) __stcg(&g_flags[mq * 32 + nt], (unsigned)(t + 1));
        {
            int tp = (t + 1 < Tt) ? t + 1 : t;
            const float* xb1 = g_xg + ((size_t)tp * Bsz + b1) * G4 + nt * 64;
            const float* xb2 = xb1 + (size_t)(b2 - b1) * G4;
#pragma unroll
            for (int s = 0; s < 4; ++s) {
                int u = 4 * s + p;
                xr[0][0][s] = __ldcs((const float2*)(xb1 + 2 * u));
                xr[1][0][s] = __ldcs((const float2*)(xb1 + 32 + 2 * u));
                xr[0][1][s] = __ldcs((const float2*)(xb2 + 2 * u));
                xr[1][1][s] = __ldcs((const float2*)(xb2 + 32 + 2 * u));
            }
        }
        if (w == 0) {
            const unsigned tgt = (unsigned)(t + 1);
            const unsigned* fp = &g_flags[mq * 32 + lane];
            while (true) {
                unsigned v = ldcg_poll(fp);          // asm volatile: re-loads every iter
                if (__all_sync(0xffffffffu, v >= tgt)) break;
                __nanosleep(64);
            }
            __threadfence();
        }
        __syncthreads();
    }
}

// ---------------- finalize: sum 32 partials, + b_mlp, sigmoid ----------------
__global__ void finalize(const float* __restrict__ bmlp, float* __restrict__ out) {
    int idx = blockIdx.x * blockDim.x + threadIdx.x;   // t*256 + b
    if (idx >= Tt * Bsz) return;
    int t = idx >> 8, b = idx & 255;
    const float4* pp = (const float4*)(g_part + (size_t)idx * 32);
    float s = bmlp[0];
#pragma unroll
    for (int qq = 0; qq < 8; qq++) {
        float4 v = pp[qq];
        s += (v.x + v.y) + (v.z + v.w);
    }
    out[(size_t)b * Tt + t] = 1.0f / (1.0f + __expf(-s));
}

// ---------------- launch ----------------
extern "C" void kernel_launch(void* const* d_in, const int* in_sizes, int n_in,
                              void* d_out, int out_size) {
    const float* x    = (const float*)d_in[0];
    const float* Wih  = (const float*)d_in[1];
    const float* Whh  = (const float*)d_in[2];
    const float* bih  = (const float*)d_in[3];
    const float* bhh  = (const float*)d_in[4];
    const float* Wmlp = (const float*)d_in[5];
    const float* bmlp = (const float*)d_in[6];
    float* out = (float*)d_out;

    const int smem_lstm  = 2 * 64 * PADK * 2;                 // 133120
    const int smem_xgate = 2 * 64 * PADD * 2 + 64 * 4;        // 67840
    cudaFuncSetAttribute(lstm_persist, cudaFuncAttributeMaxDynamicSharedMemorySize,
                         smem_lstm);
    cudaFuncSetAttribute(xgate_mma, cudaFuncAttributeMaxDynamicSharedMemorySize,
                         smem_xgate);

    init_state<<<512, 256>>>();
    convert_x<<<dim3(Tt / 32, Dd / 32, Bsz), 256>>>(x);
    convert_w<<<G4 * Dd / 256, 256>>>(Wih, bih, bhh);
    xgate_mma<<<dim3(G4 / 64, Tt / 64, Bsz), 128, smem_xgate>>>(0);
    lstm_persist<<<NBLK, 128, smem_lstm>>>(Whh, Wmlp);
    finalize<<<512, 256>>>(bmlp, out);
}